// round 4
// baseline (speedup 1.0000x reference)
#include <cuda_runtime.h>
#include <cuda_bf16.h>
#include <math.h>

#define B_   16
#define T_   500
#define D_   512
#define N_   128
#define E_   640
#define H_   1024
#define A_   1024
#define P_   1024
#define V_   10025
#define KIH  1152              // E_ + D_
#define KRO  2176              // H_ + E_ + D_
#define ZH_  0.05f
#define NB_  148               // persistent grid (== SM count floor)

// ----------------------------- scratch ------------------------------------
__device__ float g_encctx[B_ * T_ * A_];          // enc @ W_enc_ctx^T + b
__device__ float g_invf[B_ * T_];                 // 0.5 * sigmoid(enc @ w_f)
__device__ float g_h[B_ * H_];
__device__ float g_ctx[B_ * D_];
__device__ float g_accum[B_ * T_];
__device__ float g_energy[B_ * T_];
__device__ float g_st[B_ * A_];                   // s_t
__device__ float g_gemb[B_ * N_ * 3 * H_];        // emb-part of gates + biases
__device__ float g_rin[B_ * N_ * KRO];            // [h | emb | ctx] rows
__device__ float g_ro[B_ * N_ * (P_ / 2)];        // post-maxout readout
__device__ float g_wih_e[3 * H_ * E_];            // packed i,g,o rows, emb cols
__device__ float g_wc[3 * H_ * D_];               // packed i,g,o rows, ctx cols
__device__ float g_b3[3 * H_];                    // b_ih + b_hh (i,g,o)
__device__ int   g_lab64;
__device__ unsigned g_barA;                       // barrier arrive counter
__device__ unsigned g_barG;                       // barrier generation

// ----------------------------- helpers ------------------------------------
__device__ __forceinline__ float fsig(float x) {
    return __fdividef(1.0f, 1.0f + __expf(-x));
}
__device__ __forceinline__ float ftanh(float x) {      // exact-ish (cell)
    float a = fabsf(x);
    float e = __expf(-2.0f * a);
    float r = __fdividef(1.0f - e, 1.0f + e);
    return copysignf(r, x);
}
__device__ __forceinline__ float tanha(float x) {      // HW approx (energies)
    float y;
    asm("tanh.approx.f32 %0, %1;" : "=f"(y) : "f"(x));
    return y;
}

// stateless software grid barrier (all NB_ blocks co-resident: grid <= #SM)
__device__ __forceinline__ void gridbar() {
    __syncthreads();
    if (threadIdx.x == 0) {
        unsigned gen = *(volatile unsigned*)&g_barG;
        __threadfence();
        unsigned a = atomicAdd(&g_barA, 1u);
        if (a == (unsigned)(gridDim.x - 1)) {
            *(volatile unsigned*)&g_barA = 0u;
            __threadfence();
            atomicAdd(&g_barG, 1u);
        } else {
            while (*(volatile unsigned*)&g_barG == gen) __nanosleep(64);
        }
        __threadfence();
    }
    __syncthreads();
}

// ------------------------ labels dtype detection ---------------------------
__global__ void k_detect(const int* __restrict__ lab32) {
    int ok = 1;
    for (int i = threadIdx.x; i < 1024; i += blockDim.x)
        if (lab32[2 * i + 1] != 0) ok = 0;
    int all = __syncthreads_and(ok);
    if (threadIdx.x == 0) g_lab64 = all;
}

// ------------------ shifted embedding gather into g_rin --------------------
__global__ void k_gather(const void* __restrict__ labels,
                         const float* __restrict__ embed) {
    int row = blockIdx.x;                  // b*N_ + n
    int n = row & (N_ - 1);
    int b = row >> 7;
    float4* dst = (float4*)(g_rin + (size_t)row * KRO + H_);
    if (n == 0) {
        for (int k = threadIdx.x; k < E_ / 4; k += blockDim.x)
            dst[k] = make_float4(0.f, 0.f, 0.f, 0.f);
        return;
    }
    int idx = b * N_ + n - 1;
    int lab = g_lab64 ? (int)((const long long*)labels)[idx]
                      : ((const int*)labels)[idx];
    if (lab < 0) lab = 0;
    if (lab >= V_) lab = V_ - 1;
    const float4* src = (const float4*)(embed + (size_t)lab * E_);
    for (int k = threadIdx.x; k < E_ / 4; k += blockDim.x) dst[k] = src[k];
}

// ---------------- pack W_ih rows (drop f gate) + fold biases ---------------
__global__ void k_pack(const float* __restrict__ W_ih,
                       const float* __restrict__ b_ih,
                       const float* __restrict__ b_hh) {
    int jj = blockIdx.x;                         // 0..3071 (i,g,o)
    int g = jj >> 10;
    int src = (g == 0) ? jj : jj + 1024;         // skip f rows [1024,2048)
    const float* s = W_ih + (size_t)src * KIH;
    for (int k = threadIdx.x; k < E_; k += 256)
        g_wih_e[(size_t)jj * E_ + k] = s[k];
    for (int k = threadIdx.x; k < D_; k += 256)
        g_wc[(size_t)jj * D_ + k] = s[E_ + k];
    if (threadIdx.x == 0) g_b3[jj] = b_ih[src] + b_hh[src];
}

// ----------------------- inverse fertility ---------------------------------
__global__ void __launch_bounds__(256) k_invf(const float* __restrict__ enc,
                                              const float* __restrict__ wf) {
    __shared__ float wsh[D_];
    int tid = threadIdx.x;
    for (int i = tid; i < D_; i += 256) wsh[i] = wf[i];
    __syncthreads();
    int row  = blockIdx.x * 8 + (tid >> 5);
    int lane = tid & 31;
    if (row >= B_ * T_) return;
    const float4* ep = (const float4*)(enc + (size_t)row * D_);
    const float4* wp = (const float4*)wsh;
    float acc = 0.0f;
#pragma unroll
    for (int i = 0; i < 4; i++) {
        float4 e = ep[i * 32 + lane];
        float4 w = wp[i * 32 + lane];
        acc = fmaf(e.x, w.x, fmaf(e.y, w.y, fmaf(e.z, w.z, fmaf(e.w, w.w, acc))));
    }
#pragma unroll
    for (int o = 16; o; o >>= 1) acc += __shfl_down_sync(0xffffffffu, acc, o);
    if (lane == 0) g_invf[row] = 0.5f * fsig(acc);
}

// --------------- generic fp32 SGEMM C = A·B^T + bias (lda param) -----------
// mode 0: plain; mode 1: fused MaxOut(2) (ldc = N/2)
__global__ void __launch_bounds__(256) k_sgemm(const float* __restrict__ A,
                                               int lda,
                                               const float* __restrict__ Bm,
                                               const float* __restrict__ bias,
                                               float* __restrict__ C,
                                               int M, int N, int K, int ldc,
                                               int mode) {
    __shared__ float As[8][128];
    __shared__ float Bs[8][128];
    int tid = threadIdx.x;
    int row0 = blockIdx.y * 128, col0 = blockIdx.x * 128;
    int tx = tid & 15, ty = tid >> 4;
    float acc[8][8];
#pragma unroll
    for (int i = 0; i < 8; i++)
#pragma unroll
        for (int j = 0; j < 8; j++) acc[i][j] = 0.0f;
    int lr = tid >> 1;
    int lq = (tid & 1) * 4;
    const float* Ap = A  + (size_t)(row0 + lr) * lda + lq;
    const float* Bp = Bm + (size_t)(col0 + lr) * K + lq;
    bool avalid = (row0 + lr) < M;
    bool bvalid = (col0 + lr) < N;
    for (int k0 = 0; k0 < K; k0 += 8) {
        float4 av = avalid ? *(const float4*)(Ap + k0) : make_float4(0, 0, 0, 0);
        float4 bv = bvalid ? *(const float4*)(Bp + k0) : make_float4(0, 0, 0, 0);
        As[lq + 0][lr] = av.x; As[lq + 1][lr] = av.y;
        As[lq + 2][lr] = av.z; As[lq + 3][lr] = av.w;
        Bs[lq + 0][lr] = bv.x; Bs[lq + 1][lr] = bv.y;
        Bs[lq + 2][lr] = bv.z; Bs[lq + 3][lr] = bv.w;
        __syncthreads();
#pragma unroll
        for (int k = 0; k < 8; k++) {
            float ar[8], br[8];
            *(float4*)(ar)     = *(const float4*)&As[k][ty * 8];
            *(float4*)(ar + 4) = *(const float4*)&As[k][ty * 8 + 4];
            *(float4*)(br)     = *(const float4*)&Bs[k][tx * 8];
            *(float4*)(br + 4) = *(const float4*)&Bs[k][tx * 8 + 4];
#pragma unroll
            for (int i = 0; i < 8; i++)
#pragma unroll
                for (int j = 0; j < 8; j++)
                    acc[i][j] = fmaf(ar[i], br[j], acc[i][j]);
        }
        __syncthreads();
    }
    if (mode == 0) {
#pragma unroll
        for (int i = 0; i < 8; i++) {
            int m = row0 + ty * 8 + i;
            if (m >= M) break;
#pragma unroll
            for (int j = 0; j < 8; j++) {
                int nn = col0 + tx * 8 + j;
                if (nn < N) C[(size_t)m * ldc + nn] = acc[i][j] + bias[nn];
            }
        }
    } else {
#pragma unroll
        for (int i = 0; i < 8; i++) {
            int m = row0 + ty * 8 + i;
            if (m >= M) break;
#pragma unroll
            for (int p = 0; p < 4; p++) {
                int nn = col0 + tx * 8 + p * 2;
                float v0 = acc[i][p * 2]     + bias[nn];
                float v1 = acc[i][p * 2 + 1] + bias[nn + 1];
                C[(size_t)m * ldc + (nn >> 1)] = fmaxf(v0, v1);
            }
        }
    }
}

// ================= persistent recurrence kernel (all 128 steps) ============
__global__ void __launch_bounds__(256) k_loop(const float* __restrict__ enc,
                                              const int* __restrict__ seqlen,
                                              const float* __restrict__ v_att,
                                              const float* __restrict__ W_fb,
                                              const float* __restrict__ W_s) {
    __shared__ float sh_v[A_], sh_f[A_], sh_s[A_], sh_h[H_];
    __shared__ float sh_ctx[D_];
    __shared__ float sh_w[512];
    __shared__ float sh_red[256];
    int tid = threadIdx.x;
    int bk  = blockIdx.x;
    int gw  = bk * 256 + tid;
    int b   = gw >> 11;                       // block-uniform (2048 | 256·8)

    for (int i = tid; i < A_; i += 256) { sh_v[i] = v_att[i]; sh_f[i] = W_fb[i]; }
    // init recurrent state
    for (int i = gw; i < B_ * H_; i += NB_ * 256) g_h[i] = 0.0f;
    for (int i = gw; i < B_ * D_; i += NB_ * 256) g_ctx[i] = 0.0f;
    for (int i = gw; i < B_ * T_; i += NB_ * 256) g_accum[i] = 0.0f;
    gridbar();

    for (int n = 0; n < N_; n++) {
        // ---------- phase A: gates(ctx part) + activations -> h ------------
        if (b < B_)
            for (int i = tid; i < D_; i += 256) sh_ctx[i] = g_ctx[b * D_ + i];
        __syncthreads();
        if (gw < 32768) {
            int j = (gw >> 1) & 1023, half = gw & 1;
            const float4* c4 = (const float4*)sh_ctx + half * 64;
            float acc0 = 0.f, acc1 = 0.f, acc2 = 0.f;
            {
                const float4* w0 = (const float4*)&g_wc[(size_t)j * D_]            + half * 64;
                const float4* w1 = (const float4*)&g_wc[(size_t)(1024 + j) * D_]   + half * 64;
                const float4* w2 = (const float4*)&g_wc[(size_t)(2048 + j) * D_]   + half * 64;
#pragma unroll 8
                for (int kk = 0; kk < 64; kk++) {
                    float4 c = c4[kk];
                    float4 a = w0[kk], g2 = w1[kk], o = w2[kk];
                    acc0 = fmaf(a.x, c.x, fmaf(a.y, c.y, fmaf(a.z, c.z, fmaf(a.w, c.w, acc0))));
                    acc1 = fmaf(g2.x, c.x, fmaf(g2.y, c.y, fmaf(g2.z, c.z, fmaf(g2.w, c.w, acc1))));
                    acc2 = fmaf(o.x, c.x, fmaf(o.y, c.y, fmaf(o.z, c.z, fmaf(o.w, c.w, acc2))));
                }
            }
            acc0 += __shfl_xor_sync(0xffffffffu, acc0, 1);
            acc1 += __shfl_xor_sync(0xffffffffu, acc1, 1);
            acc2 += __shfl_xor_sync(0xffffffffu, acc2, 1);
            if (half == 0) {
                size_t row = (size_t)(b * N_ + n) * (3 * H_);
                float gi = acc0 + g_gemb[row + j];
                float gg = acc1 + g_gemb[row + H_ + j];
                float go = acc2 + g_gemb[row + 2 * H_ + j];
                float c_new = fsig(gi) * ftanh(gg);
                float h_new = fsig(go) * ftanh(c_new);
                float h = ZH_ * g_h[b * H_ + j] + (1.0f - ZH_) * h_new;
                g_h[b * H_ + j] = h;
                g_rin[(size_t)(b * N_ + n) * KRO + j] = h;
            }
        }
        gridbar();

        // ---------- phase B: s_t = h @ W_s^T -------------------------------
        if (b < B_)
            for (int i = tid; i < H_; i += 256) sh_h[i] = g_h[b * H_ + i];
        __syncthreads();
        if (gw < 32768) {
            int a_ = (gw >> 1) & 1023, half = gw & 1;
            const float4* h4 = (const float4*)sh_h + half * 128;
            const float4* wr = (const float4*)(W_s + (size_t)a_ * H_) + half * 128;
            float acc = 0.f;
#pragma unroll 8
            for (int kk = 0; kk < 128; kk++) {
                float4 w = wr[kk], h = h4[kk];
                acc = fmaf(w.x, h.x, fmaf(w.y, h.y, fmaf(w.z, h.z, fmaf(w.w, h.w, acc))));
            }
            acc += __shfl_xor_sync(0xffffffffu, acc, 1);
            if (half == 0) g_st[b * A_ + a_] = acc;
        }
        gridbar();

        // ---------- phase C: attention energies ----------------------------
        for (int tile = bk; tile < 512; tile += NB_) {
            int tb = tile >> 5, tt = tile & 31;     // 16 t per tile
            __syncthreads();
            for (int i = tid; i < A_; i += 256) sh_s[i] = g_st[tb * A_ + i];
            __syncthreads();
            int w = tid >> 5, lane = tid & 31;
            int Tb = seqlen[tb];
            const float4* s4 = (const float4*)sh_s;
            const float4* v4 = (const float4*)sh_v;
            const float4* f4 = (const float4*)sh_f;
#pragma unroll
            for (int u = 0; u < 2; u++) {
                int t = tt * 16 + w * 2 + u;
                if (t >= T_) continue;
                float a = g_accum[tb * T_ + t];
                const float4* ec = (const float4*)g_encctx
                                 + (size_t)(tb * T_ + t) * 256;
                float acc = 0.f;
#pragma unroll
                for (int kk = 0; kk < 8; kk++) {
                    float4 e = ec[kk * 32 + lane];
                    float4 sv = s4[kk * 32 + lane];
                    float4 fv = f4[kk * 32 + lane];
                    float4 vv = v4[kk * 32 + lane];
                    acc += vv.x * tanha(e.x + sv.x + a * fv.x);
                    acc += vv.y * tanha(e.y + sv.y + a * fv.y);
                    acc += vv.z * tanha(e.z + sv.z + a * fv.z);
                    acc += vv.w * tanha(e.w + sv.w + a * fv.w);
                }
#pragma unroll
                for (int o = 16; o; o >>= 1)
                    acc += __shfl_down_sync(0xffffffffu, acc, o);
                if (lane == 0)
                    g_energy[tb * T_ + t] = (t < Tb) ? acc : -1e30f;
            }
        }
        gridbar();

        // ---------- phase D: softmax + context + fertility accum -----------
        if (bk < 128) {
            int db = bk >> 3, ch = bk & 7;          // 8 chunks of 64 dims
            float m = -1e30f;
            for (int t = tid; t < T_; t += 256)
                m = fmaxf(m, g_energy[db * T_ + t]);
            sh_red[tid] = m; __syncthreads();
            for (int o = 128; o; o >>= 1) {
                if (tid < o) sh_red[tid] = fmaxf(sh_red[tid], sh_red[tid + o]);
                __syncthreads();
            }
            float mx = sh_red[0]; __syncthreads();
            float s = 0.f;
            for (int t = tid; t < T_; t += 256) {
                float e = __expf(g_energy[db * T_ + t] - mx);
                sh_w[t] = e;
                s += e;
            }
            sh_red[tid] = s; __syncthreads();
            for (int o = 128; o; o >>= 1) {
                if (tid < o) sh_red[tid] += sh_red[tid + o];
                __syncthreads();
            }
            float inv = __fdividef(1.0f, sh_red[0]); __syncthreads();
            for (int t = tid; t < T_; t += 256) sh_w[t] *= inv;
            __syncthreads();
            int dl = tid & 63, part = tid >> 6;
            int d = ch * 64 + dl;
            float acc = 0.f;
            for (int t = part; t < T_; t += 4)
                acc = fmaf(sh_w[t], enc[(size_t)(db * T_ + t) * D_ + d], acc);
            sh_red[tid] = acc; __syncthreads();
            if (tid < 64) {
                float v = sh_red[tid] + sh_red[64 + tid]
                        + sh_red[128 + tid] + sh_red[192 + tid];
                int dd = ch * 64 + tid;
                g_ctx[db * D_ + dd] = v;
                g_rin[(size_t)(db * N_ + n) * KRO + H_ + E_ + dd] = v;
            }
            if (ch == 0)
                for (int t = tid; t < T_; t += 256)
                    g_accum[db * T_ + t] += sh_w[t] * g_invf[db * T_ + t];
        }
        gridbar();
    }
}

// ----------------------------- launch --------------------------------------
extern "C" void kernel_launch(void* const* d_in, const int* in_sizes, int n_in,
                              void* d_out, int out_size) {
    const float* enc     = (const float*)d_in[0];
    const void*  labels  =               d_in[1];
    const int*   seqlen  = (const int*)  d_in[2];
    const float* embed   = (const float*)d_in[3];
    const float* W_ih    = (const float*)d_in[4];
    const float* b_ih    = (const float*)d_in[5];
    const float* b_hh    = (const float*)d_in[6];
    const float* W_s     = (const float*)d_in[7];
    const float* W_encc  = (const float*)d_in[8];
    const float* b_encc  = (const float*)d_in[9];
    const float* v_att   = (const float*)d_in[10];
    const float* W_invf  = (const float*)d_in[11];
    const float* W_fb    = (const float*)d_in[12];
    const float* W_ro    = (const float*)d_in[13];
    const float* b_ro    = (const float*)d_in[14];
    const float* W_out   = (const float*)d_in[15];
    const float* b_out   = (const float*)d_in[16];
    float* out = (float*)d_out;

    float* encctx; cudaGetSymbolAddress((void**)&encctx, g_encctx);
    float* rin;    cudaGetSymbolAddress((void**)&rin,    g_rin);
    float* ro;     cudaGetSymbolAddress((void**)&ro,     g_ro);
    float* gemb;   cudaGetSymbolAddress((void**)&gemb,   g_gemb);
    float* wihe;   cudaGetSymbolAddress((void**)&wihe,   g_wih_e);
    float* b3;     cudaGetSymbolAddress((void**)&b3,     g_b3);

    k_detect<<<1, 256>>>((const int*)labels);
    k_gather<<<B_ * N_, 160>>>(labels, embed);
    k_pack<<<3 * H_, 256>>>(W_ih, b_ih, b_hh);
    k_invf<<<(B_ * T_ + 7) / 8, 256>>>(enc, W_invf);

    // enc_ctx = enc @ W_enc_ctx^T + b  [8000 x 1024]
    k_sgemm<<<dim3(A_ / 128, (B_ * T_ + 127) / 128), 256>>>(
        enc, D_, W_encc, b_encc, encctx, B_ * T_, A_, D_, A_, 0);
    // gemb = emb @ W_e^T + (b_ih+b_hh)  [2048 x 3072]
    k_sgemm<<<dim3(3 * H_ / 128, (B_ * N_) / 128), 256>>>(
        rin + H_, KRO, wihe, b3, gemb, B_ * N_, 3 * H_, E_, 3 * H_, 0);

    // entire 128-step recurrence in one persistent kernel
    k_loop<<<NB_, 256>>>(enc, seqlen, v_att, W_fb, W_s);

    // readout (+MaxOut) then vocab projection
    k_sgemm<<<dim3(P_ / 128, (B_ * N_) / 128), 256>>>(
        rin, KRO, W_ro, b_ro, ro, B_ * N_, P_, KRO, P_ / 2, 1);
    k_sgemm<<<dim3((V_ + 127) / 128, (B_ * N_) / 128), 256>>>(
        ro, P_ / 2, W_out, b_out, out, B_ * N_, V_, P_ / 2, V_, 0);
}

// round 5
// speedup vs baseline: 1.3654x; 1.3654x over previous
#include <cuda_runtime.h>
#include <cuda_bf16.h>
#include <math.h>

#define B_   16
#define T_   500
#define D_   512
#define N_   128
#define E_   640
#define H_   1024
#define A_   1024
#define P_   1024
#define V_   10025
#define KIH  1152              // E_ + D_
#define KRO  2176              // H_ + E_ + D_
#define ZH_  0.05f
#define NB_  148               // persistent grid (<= SM count)

// dynamic smem layout (bytes)
#define SM_STAGE 0             // 8192 floats (32 KB)
#define SM_RED   32768         // 4352 floats (17 KB)
#define SM_V     50176         // 1024 floats
#define SM_F     54272         // 1024 floats
#define SM_TOT   58368

// ----------------------------- scratch ------------------------------------
__device__ float g_encctx[B_ * T_ * A_];          // enc @ W_enc_ctx^T + b
__device__ float g_invf[B_ * T_];                 // 0.5 * sigmoid(enc @ w_f)
__device__ float g_h_t[H_ * B_];                  // h transposed [k][b]
__device__ float g_ctx_t[D_ * B_];                // ctx transposed [d][b]
__device__ float g_accum[B_ * T_];
__device__ float g_energy[B_ * T_];
__device__ float g_st[B_ * A_];                   // s_t [b][a]
__device__ float g_gemb[B_ * N_ * 3 * H_];        // emb-part of gates + biases
__device__ float g_rin[B_ * N_ * KRO];            // [h | emb | ctx] rows
__device__ float g_ro[B_ * N_ * (P_ / 2)];        // post-maxout readout
__device__ float g_wih_e[3 * H_ * E_];            // packed i,g,o rows (emb cols)
__device__ float g_wct[D_ * 3 * H_];              // ctx-part, k-major [512][3072]
__device__ float g_ws_t[H_ * A_];                 // W_s^T  [k][a]
__device__ float g_b3[3 * H_];                    // b_ih + b_hh (i,g,o)
__device__ int   g_lab64;
__device__ unsigned g_barA;
__device__ unsigned g_barG;

// ----------------------------- helpers ------------------------------------
__device__ __forceinline__ float fsig(float x) {
    return __fdividef(1.0f, 1.0f + __expf(-x));
}
__device__ __forceinline__ float ftanh(float x) {      // accurate (cell)
    float a = fabsf(x);
    float e = __expf(-2.0f * a);
    float r = __fdividef(1.0f - e, 1.0f + e);
    return copysignf(r, x);
}
__device__ __forceinline__ float tanha(float x) {      // HW approx (energies)
    float y;
    asm("tanh.approx.f32 %0, %1;" : "=f"(y) : "f"(x));
    return y;
}

// software grid barrier (all NB_ blocks co-resident)
__device__ __forceinline__ void gridbar() {
    __threadfence();
    __syncthreads();
    if (threadIdx.x == 0) {
        unsigned gen = *(volatile unsigned*)&g_barG;
        unsigned a = atomicAdd(&g_barA, 1u);
        if (a == (unsigned)(gridDim.x - 1)) {
            *(volatile unsigned*)&g_barA = 0u;
            __threadfence();
            atomicAdd(&g_barG, 1u);
        } else {
            while (*(volatile unsigned*)&g_barG == gen) __nanosleep(32);
        }
        __threadfence();
    }
    __syncthreads();
}

// ------------------------ labels dtype detection ---------------------------
__global__ void k_detect(const int* __restrict__ lab32) {
    int ok = 1;
    for (int i = threadIdx.x; i < 1024; i += blockDim.x)
        if (lab32[2 * i + 1] != 0) ok = 0;
    int all = __syncthreads_and(ok);
    if (threadIdx.x == 0) g_lab64 = all;
}

// ------------------ shifted embedding gather into g_rin --------------------
__global__ void k_gather(const void* __restrict__ labels,
                         const float* __restrict__ embed) {
    int row = blockIdx.x;                  // b*N_ + n
    int n = row & (N_ - 1);
    int b = row >> 7;
    float4* dst = (float4*)(g_rin + (size_t)row * KRO + H_);
    if (n == 0) {
        for (int k = threadIdx.x; k < E_ / 4; k += blockDim.x)
            dst[k] = make_float4(0.f, 0.f, 0.f, 0.f);
        return;
    }
    int idx = b * N_ + n - 1;
    int lab = g_lab64 ? (int)((const long long*)labels)[idx]
                      : ((const int*)labels)[idx];
    if (lab < 0) lab = 0;
    if (lab >= V_) lab = V_ - 1;
    const float4* src = (const float4*)(embed + (size_t)lab * E_);
    for (int k = threadIdx.x; k < E_ / 4; k += blockDim.x) dst[k] = src[k];
}

// ------------- pack emb-part of W_ih rows (drop f) + fold biases -----------
__global__ void k_pack(const float* __restrict__ W_ih,
                       const float* __restrict__ b_ih,
                       const float* __restrict__ b_hh) {
    int jj = blockIdx.x;                         // 0..3071 (i,g,o)
    int src = (jj < 1024) ? jj : jj + 1024;      // skip f rows [1024,2048)
    const float* s = W_ih + (size_t)src * KIH;
    for (int k = threadIdx.x; k < E_; k += 256)
        g_wih_e[(size_t)jj * E_ + k] = s[k];
    if (threadIdx.x == 0) g_b3[jj] = b_ih[src] + b_hh[src];
}

// ---------- transpose ctx-part of W_ih into g_wct [512][3072] --------------
__global__ void k_twct(const float* __restrict__ W_ih) {
    __shared__ float tl[32][33];
    int gc0 = blockIdx.x * 32, k0 = blockIdx.y * 32;
    int tx = threadIdx.x, ty = threadIdx.y;
    for (int i = ty; i < 32; i += 8) {
        int gc = gc0 + i;
        int src = (gc < 1024) ? gc : gc + 1024;
        tl[i][tx] = W_ih[(size_t)src * KIH + E_ + k0 + tx];
    }
    __syncthreads();
    for (int i = ty; i < 32; i += 8)
        g_wct[(size_t)(k0 + i) * (3 * H_) + gc0 + tx] = tl[tx][i];
}

// ---------------- transpose W_s into g_ws_t [k][a] -------------------------
__global__ void k_tws(const float* __restrict__ W_s) {
    __shared__ float tl[32][33];
    int j0 = blockIdx.x * 32, k0 = blockIdx.y * 32;
    int tx = threadIdx.x, ty = threadIdx.y;
    for (int i = ty; i < 32; i += 8)
        tl[i][tx] = W_s[(size_t)(j0 + i) * H_ + k0 + tx];
    __syncthreads();
    for (int i = ty; i < 32; i += 8)
        g_ws_t[(size_t)(k0 + i) * A_ + j0 + tx] = tl[tx][i];
}

// ----------------------- inverse fertility ---------------------------------
__global__ void __launch_bounds__(256) k_invf(const float* __restrict__ enc,
                                              const float* __restrict__ wf) {
    __shared__ float wsh[D_];
    int tid = threadIdx.x;
    for (int i = tid; i < D_; i += 256) wsh[i] = wf[i];
    __syncthreads();
    int row  = blockIdx.x * 8 + (tid >> 5);
    int lane = tid & 31;
    if (row >= B_ * T_) return;
    const float4* ep = (const float4*)(enc + (size_t)row * D_);
    const float4* wp = (const float4*)wsh;
    float acc = 0.0f;
#pragma unroll
    for (int i = 0; i < 4; i++) {
        float4 e = ep[i * 32 + lane];
        float4 w = wp[i * 32 + lane];
        acc = fmaf(e.x, w.x, fmaf(e.y, w.y, fmaf(e.z, w.z, fmaf(e.w, w.w, acc))));
    }
#pragma unroll
    for (int o = 16; o; o >>= 1) acc += __shfl_down_sync(0xffffffffu, acc, o);
    if (lane == 0) g_invf[row] = 0.5f * fsig(acc);
}

// --------------- generic fp32 SGEMM C = A·B^T + bias -----------------------
__global__ void __launch_bounds__(256) k_sgemm(const float* __restrict__ A,
                                               int lda,
                                               const float* __restrict__ Bm,
                                               const float* __restrict__ bias,
                                               float* __restrict__ C,
                                               int M, int N, int K, int ldc,
                                               int mode) {
    __shared__ float As[8][128];
    __shared__ float Bs[8][128];
    int tid = threadIdx.x;
    int row0 = blockIdx.y * 128, col0 = blockIdx.x * 128;
    int tx = tid & 15, ty = tid >> 4;
    float acc[8][8];
#pragma unroll
    for (int i = 0; i < 8; i++)
#pragma unroll
        for (int j = 0; j < 8; j++) acc[i][j] = 0.0f;
    int lr = tid >> 1;
    int lq = (tid & 1) * 4;
    const float* Ap = A  + (size_t)(row0 + lr) * lda + lq;
    const float* Bp = Bm + (size_t)(col0 + lr) * K + lq;
    bool avalid = (row0 + lr) < M;
    bool bvalid = (col0 + lr) < N;
    for (int k0 = 0; k0 < K; k0 += 8) {
        float4 av = avalid ? *(const float4*)(Ap + k0) : make_float4(0, 0, 0, 0);
        float4 bv = bvalid ? *(const float4*)(Bp + k0) : make_float4(0, 0, 0, 0);
        As[lq + 0][lr] = av.x; As[lq + 1][lr] = av.y;
        As[lq + 2][lr] = av.z; As[lq + 3][lr] = av.w;
        Bs[lq + 0][lr] = bv.x; Bs[lq + 1][lr] = bv.y;
        Bs[lq + 2][lr] = bv.z; Bs[lq + 3][lr] = bv.w;
        __syncthreads();
#pragma unroll
        for (int k = 0; k < 8; k++) {
            float ar[8], br[8];
            *(float4*)(ar)     = *(const float4*)&As[k][ty * 8];
            *(float4*)(ar + 4) = *(const float4*)&As[k][ty * 8 + 4];
            *(float4*)(br)     = *(const float4*)&Bs[k][tx * 8];
            *(float4*)(br + 4) = *(const float4*)&Bs[k][tx * 8 + 4];
#pragma unroll
            for (int i = 0; i < 8; i++)
#pragma unroll
                for (int j = 0; j < 8; j++)
                    acc[i][j] = fmaf(ar[i], br[j], acc[i][j]);
        }
        __syncthreads();
    }
    if (mode == 0) {
#pragma unroll
        for (int i = 0; i < 8; i++) {
            int m = row0 + ty * 8 + i;
            if (m >= M) break;
#pragma unroll
            for (int j = 0; j < 8; j++) {
                int nn = col0 + tx * 8 + j;
                if (nn < N) C[(size_t)m * ldc + nn] = acc[i][j] + bias[nn];
            }
        }
    } else {
#pragma unroll
        for (int i = 0; i < 8; i++) {
            int m = row0 + ty * 8 + i;
            if (m >= M) break;
#pragma unroll
            for (int p = 0; p < 4; p++) {
                int nn = col0 + tx * 8 + p * 2;
                float v0 = acc[i][p * 2]     + bias[nn];
                float v1 = acc[i][p * 2 + 1] + bias[nn + 1];
                C[(size_t)m * ldc + (nn >> 1)] = fmaxf(v0, v1);
            }
        }
    }
}

// ================= persistent recurrence kernel (all 128 steps) ============
__global__ void __launch_bounds__(256) k_loop(const float* __restrict__ enc,
                                              const int* __restrict__ seqlen,
                                              const float* __restrict__ v_att,
                                              const float* __restrict__ W_fb) {
    extern __shared__ char dynbuf[];
    float* sm_stage = (float*)(dynbuf + SM_STAGE);   // 8192 floats
    float* sm_red   = (float*)(dynbuf + SM_RED);     // 4352 floats
    float* sm_v     = (float*)(dynbuf + SM_V);       // 1024
    float* sm_f     = (float*)(dynbuf + SM_F);       // 1024

    int tid = threadIdx.x;
    int bk  = blockIdx.x;
    int gw  = bk * 256 + tid;

    for (int i = tid; i < A_; i += 256) { sm_v[i] = v_att[i]; sm_f[i] = W_fb[i]; }
    for (int i = gw; i < H_ * B_; i += NB_ * 256) g_h_t[i]   = 0.0f;
    for (int i = gw; i < D_ * B_; i += NB_ * 256) g_ctx_t[i] = 0.0f;
    for (int i = gw; i < B_ * T_; i += NB_ * 256) g_accum[i] = 0.0f;
    gridbar();

    for (int n = 0; n < N_; n++) {
        // ======== phase A: gates(ctx) + activation -> h =====================
        // 128 blocks x 8 output-j; cols = gate*8+jl (24), ks = 8 splits of 64.
        if (bk < 128) {
            for (int idx = tid; idx < D_ * B_; idx += 256)
                sm_stage[idx] = g_ctx_t[idx];            // [k][b] contiguous
            __syncthreads();
            if (tid < 192) {
                int col = tid % 24, ks = tid / 24;       // ks 0..7
                int gate = col >> 3, jl = col & 7;
                int gc = gate * 1024 + bk * 8 + jl;
                const float* wp = g_wct + (size_t)(ks * 64) * (3 * H_) + gc;
                const float4* c4 = (const float4*)(sm_stage + ks * 64 * 16);
                float acc[16];
#pragma unroll
                for (int b = 0; b < 16; b++) acc[b] = 0.0f;
#pragma unroll 4
                for (int i = 0; i < 64; i++) {
                    float w = wp[(size_t)i * (3 * H_)];
                    float4 c0 = c4[i * 4 + 0], c1 = c4[i * 4 + 1];
                    float4 c2 = c4[i * 4 + 2], c3 = c4[i * 4 + 3];
                    acc[0]  = fmaf(w, c0.x, acc[0]);  acc[1]  = fmaf(w, c0.y, acc[1]);
                    acc[2]  = fmaf(w, c0.z, acc[2]);  acc[3]  = fmaf(w, c0.w, acc[3]);
                    acc[4]  = fmaf(w, c1.x, acc[4]);  acc[5]  = fmaf(w, c1.y, acc[5]);
                    acc[6]  = fmaf(w, c1.z, acc[6]);  acc[7]  = fmaf(w, c1.w, acc[7]);
                    acc[8]  = fmaf(w, c2.x, acc[8]);  acc[9]  = fmaf(w, c2.y, acc[9]);
                    acc[10] = fmaf(w, c2.z, acc[10]); acc[11] = fmaf(w, c2.w, acc[11]);
                    acc[12] = fmaf(w, c3.x, acc[12]); acc[13] = fmaf(w, c3.y, acc[13]);
                    acc[14] = fmaf(w, c3.z, acc[14]); acc[15] = fmaf(w, c3.w, acc[15]);
                }
#pragma unroll
                for (int b = 0; b < 16; b++)
                    sm_red[ks * 384 + b * 24 + col] = acc[b];
            }
            __syncthreads();
            if (tid < 128) {
                int jl = tid >> 4, b = tid & 15;
                int j = bk * 8 + jl;
                float gi = 0.f, gg = 0.f, go = 0.f;
#pragma unroll
                for (int ks = 0; ks < 8; ks++) {
                    gi += sm_red[ks * 384 + b * 24 + jl];
                    gg += sm_red[ks * 384 + b * 24 + 8 + jl];
                    go += sm_red[ks * 384 + b * 24 + 16 + jl];
                }
                size_t row = (size_t)(b * N_ + n) * (3 * H_);
                gi += g_gemb[row + j];
                gg += g_gemb[row + H_ + j];
                go += g_gemb[row + 2 * H_ + j];
                float c_new = fsig(gi) * ftanh(gg);
                float h_new = fsig(go) * ftanh(c_new);
                float h = ZH_ * g_h_t[j * 16 + b] + (1.0f - ZH_) * h_new;
                g_h_t[j * 16 + b] = h;
                g_rin[(size_t)(b * N_ + n) * KRO + j] = h;
            }
        }
        gridbar();

        // ======== phase B: s_t = h @ W_s^T ==================================
        // 128 blocks x 8 a-cols; ks = 32 splits of 32 k (2 smem halves).
        if (bk < 128) {
            int col = tid & 7, ks = tid >> 3;            // ks 0..31
            int a0 = bk * 8;
            float acc[16];
#pragma unroll
            for (int b = 0; b < 16; b++) acc[b] = 0.0f;
#pragma unroll
            for (int half = 0; half < 2; half++) {
                __syncthreads();
                for (int idx = tid; idx < 8192; idx += 256)
                    sm_stage[idx] = g_h_t[half * 8192 + idx];
                __syncthreads();
                const float* wp = g_ws_t + (size_t)(half * 512 + ks * 16) * A_ + a0 + col;
                const float4* h4 = (const float4*)(sm_stage + ks * 16 * 16);
#pragma unroll 2
                for (int i = 0; i < 16; i++) {
                    float w = wp[(size_t)i * A_];
                    float4 h0 = h4[i * 4 + 0], h1 = h4[i * 4 + 1];
                    float4 h2 = h4[i * 4 + 2], h3 = h4[i * 4 + 3];
                    acc[0]  = fmaf(w, h0.x, acc[0]);  acc[1]  = fmaf(w, h0.y, acc[1]);
                    acc[2]  = fmaf(w, h0.z, acc[2]);  acc[3]  = fmaf(w, h0.w, acc[3]);
                    acc[4]  = fmaf(w, h1.x, acc[4]);  acc[5]  = fmaf(w, h1.y, acc[5]);
                    acc[6]  = fmaf(w, h1.z, acc[6]);  acc[7]  = fmaf(w, h1.w, acc[7]);
                    acc[8]  = fmaf(w, h2.x, acc[8]);  acc[9]  = fmaf(w, h2.y, acc[9]);
                    acc[10] = fmaf(w, h2.z, acc[10]); acc[11] = fmaf(w, h2.w, acc[11]);
                    acc[12] = fmaf(w, h3.x, acc[12]); acc[13] = fmaf(w, h3.y, acc[13]);
                    acc[14] = fmaf(w, h3.z, acc[14]); acc[15] = fmaf(w, h3.w, acc[15]);
                }
            }
#pragma unroll
            for (int b = 0; b < 16; b++)
                sm_red[ks * 132 + b * 8 + col] = acc[b];
            __syncthreads();
            if (tid < 128) {
                int c2 = tid >> 4, b = tid & 15;
                float s = 0.f;
#pragma unroll
                for (int k2 = 0; k2 < 32; k2++)
                    s += sm_red[k2 * 132 + b * 8 + c2];
                g_st[b * A_ + a0 + c2] = s;
            }
        }
        gridbar();

        // ======== phase C: attention energies ===============================
        for (int tile = bk; tile < 512; tile += NB_) {
            int tb = tile >> 5, tt = tile & 31;          // 16 t per tile
            __syncthreads();
            for (int i = tid; i < A_; i += 256) sm_stage[i] = g_st[tb * A_ + i];
            __syncthreads();
            int w = tid >> 5, lane = tid & 31;
            int Tb = seqlen[tb];
            const float4* s4 = (const float4*)sm_stage;
            const float4* v4 = (const float4*)sm_v;
            const float4* f4 = (const float4*)sm_f;
#pragma unroll
            for (int u = 0; u < 2; u++) {
                int t = tt * 16 + w * 2 + u;
                if (t >= T_) continue;
                float a = g_accum[tb * T_ + t];
                const float4* ec = (const float4*)g_encctx
                                 + (size_t)(tb * T_ + t) * 256;
                float acc = 0.f;
#pragma unroll
                for (int kk = 0; kk < 8; kk++) {
                    float4 e = ec[kk * 32 + lane];
                    float4 sv = s4[kk * 32 + lane];
                    float4 fv = f4[kk * 32 + lane];
                    float4 vv = v4[kk * 32 + lane];
                    acc += vv.x * tanha(e.x + sv.x + a * fv.x);
                    acc += vv.y * tanha(e.y + sv.y + a * fv.y);
                    acc += vv.z * tanha(e.z + sv.z + a * fv.z);
                    acc += vv.w * tanha(e.w + sv.w + a * fv.w);
                }
#pragma unroll
                for (int o = 16; o; o >>= 1)
                    acc += __shfl_down_sync(0xffffffffu, acc, o);
                if (lane == 0)
                    g_energy[tb * T_ + t] = (t < Tb) ? acc : -1e30f;
            }
        }
        gridbar();

        // ======== phase D: softmax + context + fertility accum =============
        if (bk < 128) {
            int db = bk >> 3, ch = bk & 7;               // 8 chunks x 64 dims
            float* sw = sm_stage;                        // 512 floats
            float m = -1e30f;
            for (int t = tid; t < T_; t += 256)
                m = fmaxf(m, g_energy[db * T_ + t]);
            sm_red[tid] = m; __syncthreads();
            for (int o = 128; o; o >>= 1) {
                if (tid < o) sm_red[tid] = fmaxf(sm_red[tid], sm_red[tid + o]);
                __syncthreads();
            }
            float mx = sm_red[0]; __syncthreads();
            float s = 0.f;
            for (int t = tid; t < T_; t += 256) {
                float e = __expf(g_energy[db * T_ + t] - mx);
                sw[t] = e;
                s += e;
            }
            sm_red[tid] = s; __syncthreads();
            for (int o = 128; o; o >>= 1) {
                if (tid < o) sm_red[tid] += sm_red[tid + o];
                __syncthreads();
            }
            float inv = __fdividef(1.0f, sm_red[0]); __syncthreads();
            for (int t = tid; t < T_; t += 256) sw[t] *= inv;
            __syncthreads();
            int dl = tid & 63, part = tid >> 6;
            int d = ch * 64 + dl;
            float acc = 0.f;
            for (int t = part; t < T_; t += 4)
                acc = fmaf(sw[t], enc[(size_t)(db * T_ + t) * D_ + d], acc);
            sm_red[tid] = acc; __syncthreads();
            if (tid < 64) {
                float v = sm_red[tid] + sm_red[64 + tid]
                        + sm_red[128 + tid] + sm_red[192 + tid];
                int dd = ch * 64 + tid;
                g_ctx_t[dd * 16 + db] = v;
                g_rin[(size_t)(db * N_ + n) * KRO + H_ + E_ + dd] = v;
            }
            if (ch == 0)
                for (int t = tid; t < T_; t += 256)
                    g_accum[db * T_ + t] += sw[t] * g_invf[db * T_ + t];
        }
        gridbar();
    }
}

// ----------------------------- launch --------------------------------------
extern "C" void kernel_launch(void* const* d_in, const int* in_sizes, int n_in,
                              void* d_out, int out_size) {
    const float* enc     = (const float*)d_in[0];
    const void*  labels  =               d_in[1];
    const int*   seqlen  = (const int*)  d_in[2];
    const float* embed   = (const float*)d_in[3];
    const float* W_ih    = (const float*)d_in[4];
    const float* b_ih    = (const float*)d_in[5];
    const float* b_hh    = (const float*)d_in[6];
    const float* W_s     = (const float*)d_in[7];
    const float* W_encc  = (const float*)d_in[8];
    const float* b_encc  = (const float*)d_in[9];
    const float* v_att   = (const float*)d_in[10];
    const float* W_invf  = (const float*)d_in[11];
    const float* W_fb    = (const float*)d_in[12];
    const float* W_ro    = (const float*)d_in[13];
    const float* b_ro    = (const float*)d_in[14];
    const float* W_out   = (const float*)d_in[15];
    const float* b_out   = (const float*)d_in[16];
    float* out = (float*)d_out;

    float* encctx; cudaGetSymbolAddress((void**)&encctx, g_encctx);
    float* rin;    cudaGetSymbolAddress((void**)&rin,    g_rin);
    float* ro;     cudaGetSymbolAddress((void**)&ro,     g_ro);
    float* gemb;   cudaGetSymbolAddress((void**)&gemb,   g_gemb);
    float* wihe;   cudaGetSymbolAddress((void**)&wihe,   g_wih_e);
    float* b3;     cudaGetSymbolAddress((void**)&b3,     g_b3);

    static int smem_set = 0;
    if (!smem_set) {
        cudaFuncSetAttribute(k_loop,
            cudaFuncAttributeMaxDynamicSharedMemorySize, SM_TOT);
        smem_set = 1;
    }

    k_detect<<<1, 256>>>((const int*)labels);
    k_gather<<<B_ * N_, 160>>>(labels, embed);
    k_pack<<<3 * H_, 256>>>(W_ih, b_ih, b_hh);
    { dim3 blk(32, 8); k_twct<<<dim3(96, 16), blk>>>(W_ih); }
    { dim3 blk(32, 8); k_tws <<<dim3(32, 32), blk>>>(W_s);  }
    k_invf<<<(B_ * T_ + 7) / 8, 256>>>(enc, W_invf);

    // enc_ctx = enc @ W_enc_ctx^T + b   [8000 x 1024]
    k_sgemm<<<dim3(A_ / 128, (B_ * T_ + 127) / 128), 256>>>(
        enc, D_, W_encc, b_encc, encctx, B_ * T_, A_, D_, A_, 0);
    // gemb = emb @ W_e^T + (b_ih+b_hh)  [2048 x 3072]
    k_sgemm<<<dim3(3 * H_ / 128, (B_ * N_) / 128), 256>>>(
        rin + H_, KRO, wihe, b3, gemb, B_ * N_, 3 * H_, E_, 3 * H_, 0);

    // entire 128-step recurrence in one persistent kernel
    k_loop<<<NB_, 256, SM_TOT>>>(enc, seqlen, v_att, W_fb);

    // readout (+MaxOut) then vocab projection
    k_sgemm<<<dim3(P_ / 128, (B_ * N_) / 128), 256>>>(
        rin, KRO, W_ro, b_ro, ro, B_ * N_, P_, KRO, P_ / 2, 1);
    k_sgemm<<<dim3((V_ + 127) / 128, (B_ * N_) / 128), 256>>>(
        ro, P_ / 2, W_out, b_out, out, B_ * N_, V_, P_ / 2, V_, 0);
}